// round 16
// baseline (speedup 1.0000x reference)
#include <cuda_runtime.h>
#include <cuda_fp16.h>
#include <cstdint>

#define TOKENS 64
#define IN_F   8192
#define OUT_F  8192
#define NGROUPS (IN_F / 8)     // 1024
#define KT_TILES (IN_F / 16)   // 512 k16 tiles
#define KSPLIT 4
#define NBLK   64              // N per gemm unit (4 warps x N16)
#define QCHUNK 2048            // elements per FWHT chunk (2 folded levels)

// A fragments: [kt][mt][lane] -> uint4 (4 regs of m16k16 fp16 frag)
__device__ uint4 g_xa[KT_TILES * 4 * 32];            // 1 MB
// accumulated output [token][out] (REDG target, zeroed in phase 1)
__device__ float g_acc[TOKENS * OUT_F];              // 2 MB
// device-wide phase counters (reset by last phase-3 block each run)
__device__ int g_sync1, g_sync2, g_done;

#define INV_SQRT_8192 0.011048543456039806f

__device__ __forceinline__ int SW(int i) {
    return (i & ~31) | ((i ^ (i >> 5)) & 31);
}
__device__ __forceinline__ int ld_vol(const int* p) {
    int v;
    asm volatile("ld.volatile.global.s32 %0, [%1];" : "=r"(v) : "l"(p) : "memory");
    return v;
}

#define FWHT_REG(a, N)                                            \
    _Pragma("unroll")                                             \
    for (int h = 1; h < (N); h <<= 1) {                           \
        _Pragma("unroll")                                         \
        for (int i = 0; i < (N); i++) {                           \
            if (!(i & h)) {                                       \
                float u = a[i], v = a[i ^ h];                     \
                a[i] = u + v; a[i ^ h] = u - v;                   \
            }                                                     \
        }                                                         \
    }

#define FWHT_STAGE(a, N, h)                                       \
    _Pragma("unroll")                                             \
    for (int i = 0; i < (N); i++) {                               \
        if (!(i & (h))) {                                         \
            float u = a[i], v = a[i ^ (h)];                       \
            a[i] = u + v; a[i ^ (h)] = u - v;                     \
        }                                                         \
    }

// FWHT over 2048 elements, 128 threads, 16 contiguous elems/thread.
// Phases: reg bits 0-1, smem bits 4-7, smem bits 8-10, reg bits 2-3.
#define FWHT2048_BODY(s, t, a)                                    \
    FWHT_STAGE(a, 16, 1)                                          \
    FWHT_STAGE(a, 16, 2)                                          \
    _Pragma("unroll")                                             \
    for (int i = 0; i < 16; i++)                                  \
        s[SW(16 * (t) + i)] = a[i];                               \
    __syncthreads();                                              \
    {                                                             \
        const int b2 = ((t) & 15) | (((t) >> 4) << 8);            \
        float bb[16];                                             \
        _Pragma("unroll")                                         \
        for (int m = 0; m < 16; m++)                              \
            bb[m] = s[SW(b2 + 16 * m)];                           \
        FWHT_REG(bb, 16)                                          \
        __syncthreads();                                          \
        _Pragma("unroll")                                         \
        for (int m = 0; m < 16; m++)                              \
            s[SW(b2 + 16 * m)] = bb[m];                           \
    }                                                             \
    __syncthreads();                                              \
    {                                                             \
        float g0[8], g1[8];                                       \
        _Pragma("unroll")                                         \
        for (int m = 0; m < 8; m++) {                             \
            g0[m] = s[SW((t) + 256 * m)];                         \
            g1[m] = s[SW((t) + 128 + 256 * m)];                   \
        }                                                         \
        FWHT_REG(g0, 8)                                           \
        FWHT_REG(g1, 8)                                           \
        __syncthreads();                                          \
        _Pragma("unroll")                                         \
        for (int m = 0; m < 8; m++) {                             \
            s[SW((t) + 256 * m)]       = g0[m];                   \
            s[SW((t) + 128 + 256 * m)] = g1[m];                   \
        }                                                         \
    }                                                             \
    __syncthreads();                                              \
    _Pragma("unroll")                                             \
    for (int i = 0; i < 16; i++)                                  \
        a[i] = s[SW(16 * (t) + i)];                               \
    FWHT_STAGE(a, 16, 4)                                          \
    FWHT_STAGE(a, 16, 8)

__device__ __forceinline__ void mma16816(float c[4], const uint4& a,
                                         uint32_t b0, uint32_t b1)
{
    asm volatile(
        "mma.sync.aligned.m16n8k16.row.col.f32.f16.f16.f32 "
        "{%0,%1,%2,%3},{%4,%5,%6,%7},{%8,%9},{%0,%1,%2,%3};\n"
        : "+f"(c[0]), "+f"(c[1]), "+f"(c[2]), "+f"(c[3])
        : "r"(a.x), "r"(a.y), "r"(a.z), "r"(a.w), "r"(b0), "r"(b1));
}

// ---------------------------------------------------------------------------
// ONE fused kernel. 512 blocks x 128 threads, 4 blocks/SM guaranteed
// (launch_bounds reg cap + 12.5 KB smem) -> all blocks resident, flag-sync safe.
//   phase 1 (bid<256): FWHT(x*SU)*scale -> g_xa, zero g_acc   [R13 body]
//   sync1
//   phase 2 (all):     codebook-decode fp16 mma GEMM, REDG -> g_acc
//   sync2 (bid>=256 exit)
//   phase 3 (bid<256): FWHT(g_acc) * SV/sqrt + bias -> out    [R13 body]
// ---------------------------------------------------------------------------
__global__ __launch_bounds__(128, 4) void fused_kernel(
    const float* __restrict__ x,
    const float* __restrict__ SU,
    const float* __restrict__ SV,
    const float* __restrict__ grid,
    const float* __restrict__ Wscale,
    const float* __restrict__ bias,
    const int*   __restrict__ Qidxs,
    float*       __restrict__ out)
{
    __shared__ float    s[QCHUNK];       // 8 KB (phases 1 & 3)
    __shared__ uint32_t cb[256 * 4];     // 4 KB fp16 codebook

    const int tid = threadIdx.x;
    const int bid = blockIdx.x;

    // codebook fill (independent of everything)
    for (int i = tid; i < 1024; i += 128) {
        int c = i >> 2, j = i & 3;
        __half2 h = __floats2half2_rn(grid[c * 8 + 2 * j], grid[c * 8 + 2 * j + 1]);
        cb[i] = *(uint32_t*)&h;
    }

    // =============== phase 1: input FWHT ===============
    if (bid < 256) {
        const int t = bid >> 2;
        const int q = bid & 3;
        const float* xr = x + (size_t)t * IN_F;

        // zero this block's 8 KB slice of g_acc
        {
            float4* z = (float4*)(g_acc + (size_t)bid * QCHUNK) + tid;
#pragma unroll
            for (int v = 0; v < 4; v++)
                z[v * 128] = make_float4(0.f, 0.f, 0.f, 0.f);
        }

        float a[16];
#pragma unroll
        for (int i = 0; i < 16; i++) a[i] = 0.0f;
        const int g0 = tid * 16;
#pragma unroll
        for (int jh = 0; jh < 4; jh++) {
            const float sg = (__popc(q & jh) & 1) ? -1.0f : 1.0f;
            const float4* xp = (const float4*)(xr + jh * QCHUNK + g0);
            const float4* sp = (const float4*)(SU + jh * QCHUNK + g0);
#pragma unroll
            for (int v = 0; v < 4; v++) {
                const float4 xv = xp[v];
                const float4 sv = sp[v];
                a[4*v]   += sg * xv.x * sv.x;
                a[4*v+1] += sg * xv.y * sv.y;
                a[4*v+2] += sg * xv.z * sv.z;
                a[4*v+3] += sg * xv.w * sv.w;
            }
        }

        FWHT2048_BODY(s, tid, a)

        const float scale = INV_SQRT_8192 * Wscale[0];
        const int mt   = t >> 4;
        const int mrow = t & 15;
        const int kt   = q * 128 + tid;
        uint32_t* xa = (uint32_t*)g_xa;
#pragma unroll
        for (int p = 0; p < 8; p++) {
            const int r    = p >> 2;
            const int lane = ((mrow & 7) << 2) | (p & 3);
            const int reg  = (r << 1) | (mrow >> 3);
            __half2 h = __floats2half2_rn(a[2*p] * scale, a[2*p+1] * scale);
            xa[(((kt * 4 + mt) * 32 + lane) << 2) + reg] = *(uint32_t*)&h;
        }

        __threadfence();
        __syncthreads();
        if (tid == 0) atomicAdd(&g_sync1, 1);
    }

    // =============== gemm setup + Qidxs prefetch (pre-sync) ===============
    const int lane = tid & 31;
    const int w    = tid >> 5;
    const int l4   = lane & 3;
    const int lq   = lane >> 2;
    const int ob    = bid >> 2;
    const int split = bid & 3;
    const int oW    = ob * NBLK + w * 16;

    const int ktBase = split * (KT_TILES / KSPLIT);   // 128 tiles per split
    const int ktEnd  = ktBase + (KT_TILES / KSPLIT);

    const int2* qp0 = (const int2*)(Qidxs + (size_t)(oW + lq) * NGROUPS);
    const int2* qp1 = (const int2*)(Qidxs + (size_t)(oW + 8 + lq) * NGROUPS);

    int2 qB[2][2];
    qB[0][0] = qp0[ktBase];     qB[0][1] = qp1[ktBase];
    qB[1][0] = qp0[ktBase + 1]; qB[1][1] = qp1[ktBase + 1];

    float acc[2][4][4];
#pragma unroll
    for (int n = 0; n < 2; n++)
#pragma unroll
        for (int m = 0; m < 4; m++)
#pragma unroll
            for (int r = 0; r < 4; r++) acc[n][m][r] = 0.0f;

    // =============== sync1: wait for all phase-1 blocks ===============
    if (tid == 0) {
        while (ld_vol(&g_sync1) < 256) __nanosleep(100);
    }
    __syncthreads();
    __threadfence();

    // =============== phase 2: GEMM mainloop ===============
    uint4 aB[2][4];
#pragma unroll
    for (int m = 0; m < 4; m++) {
        aB[0][m] = g_xa[((ktBase    ) * 4 + m) * 32 + lane];
        aB[1][m] = g_xa[((ktBase + 1) * 4 + m) * 32 + lane];
    }

    for (int kt = ktBase; kt < ktEnd; kt += 2) {
        {
            const uint32_t b00 = cb[(qB[0][0].x << 2) | l4];
            const uint32_t b01 = cb[(qB[0][0].y << 2) | l4];
            const uint32_t b10 = cb[(qB[0][1].x << 2) | l4];
            const uint32_t b11 = cb[(qB[0][1].y << 2) | l4];
#pragma unroll
            for (int m = 0; m < 4; m++) {
                mma16816(acc[0][m], aB[0][m], b00, b01);
                mma16816(acc[1][m], aB[0][m], b10, b11);
            }
            const int ktn = (kt + 2 < ktEnd) ? kt + 2 : ktEnd - 1;
#pragma unroll
            for (int m = 0; m < 4; m++)
                aB[0][m] = g_xa[(ktn * 4 + m) * 32 + lane];
            qB[0][0] = qp0[ktn];
            qB[0][1] = qp1[ktn];
        }
        {
            const uint32_t b00 = cb[(qB[1][0].x << 2) | l4];
            const uint32_t b01 = cb[(qB[1][0].y << 2) | l4];
            const uint32_t b10 = cb[(qB[1][1].x << 2) | l4];
            const uint32_t b11 = cb[(qB[1][1].y << 2) | l4];
#pragma unroll
            for (int m = 0; m < 4; m++) {
                mma16816(acc[0][m], aB[1][m], b00, b01);
                mma16816(acc[1][m], aB[1][m], b10, b11);
            }
            const int ktn = (kt + 3 < ktEnd) ? kt + 3 : ktEnd - 1;
#pragma unroll
            for (int m = 0; m < 4; m++)
                aB[1][m] = g_xa[(ktn * 4 + m) * 32 + lane];
            qB[1][0] = qp0[ktn];
            qB[1][1] = qp1[ktn];
        }
    }

    // REDG epilogue into g_acc (L2 atomics)
#pragma unroll
    for (int n = 0; n < 2; n++) {
        const int o = oW + n * 8 + 2 * l4;
#pragma unroll
        for (int m = 0; m < 4; m++) {
            const int t0 = m * 16 + lq;
            atomicAdd(&g_acc[(size_t)t0 * OUT_F + o],           acc[n][m][0]);
            atomicAdd(&g_acc[(size_t)t0 * OUT_F + o + 1],       acc[n][m][1]);
            atomicAdd(&g_acc[(size_t)(t0 + 8) * OUT_F + o],     acc[n][m][2]);
            atomicAdd(&g_acc[(size_t)(t0 + 8) * OUT_F + o + 1], acc[n][m][3]);
        }
    }

    __threadfence();
    __syncthreads();
    if (tid == 0) atomicAdd(&g_sync2, 1);

    if (bid >= 256) return;            // gemm-only blocks exit

    // =============== sync2: wait for all gemm work ===============
    if (tid == 0) {
        while (ld_vol(&g_sync2) < 512) __nanosleep(100);
    }
    __syncthreads();
    __threadfence();

    // =============== phase 3: output FWHT ===============
    {
        const int t = bid >> 2;
        const int q = bid & 3;
        const float* row = g_acc + (size_t)t * OUT_F;
        const int g0 = tid * 16;

        float a[16];
#pragma unroll
        for (int i = 0; i < 16; i++) a[i] = 0.0f;
#pragma unroll
        for (int jh = 0; jh < 4; jh++) {
            const float sg = (__popc(q & jh) & 1) ? -1.0f : 1.0f;
            const float4* rp = (const float4*)(row + jh * QCHUNK + g0);
#pragma unroll
            for (int v = 0; v < 4; v++) {
                const float4 rv = __ldcg(rp + v);   // bypass stale L1 zeroes
                a[4*v]   += sg * rv.x;
                a[4*v+1] += sg * rv.y;
                a[4*v+2] += sg * rv.z;
                a[4*v+3] += sg * rv.w;
            }
        }

        FWHT2048_BODY(s, tid, a)

        const int jBase = q * QCHUNK + g0;
        const float4* sv4 = (const float4*)(SV + jBase);
        const float4* bp4 = (const float4*)(bias + jBase);
        float4* op = (float4*)(out + (size_t)t * OUT_F + jBase);
#pragma unroll
        for (int v = 0; v < 4; v++) {
            const float4 sv = sv4[v];
            const float4 bv = bp4[v];
            float4 o;
            o.x = a[4*v]   * INV_SQRT_8192 * sv.x + bv.x;
            o.y = a[4*v+1] * INV_SQRT_8192 * sv.y + bv.y;
            o.z = a[4*v+2] * INV_SQRT_8192 * sv.z + bv.z;
            o.w = a[4*v+3] * INV_SQRT_8192 * sv.w + bv.w;
            op[v] = o;
        }
    }

    // last phase-3 block resets counters for next graph replay
    __syncthreads();
    if (tid == 0) {
        const int old = atomicAdd(&g_done, 1);
        if (old == 255) {
            atomicExch(&g_sync1, 0);
            atomicExch(&g_sync2, 0);
            atomicExch(&g_done,  0);
        }
    }
}

// ---------------------------------------------------------------------------
// Inputs (metadata order): x, SU, SV, grid, Wscale, bias, Qidxs
// ---------------------------------------------------------------------------
extern "C" void kernel_launch(void* const* d_in, const int* in_sizes, int n_in,
                              void* d_out, int out_size)
{
    const float* x      = (const float*)d_in[0];
    const float* SU     = (const float*)d_in[1];
    const float* SV     = (const float*)d_in[2];
    const float* grid   = (const float*)d_in[3];
    const float* Wscale = (const float*)d_in[4];
    const float* bias   = (const float*)d_in[5];
    const int*   Qidxs  = (const int*)  d_in[6];
    float*       out    = (float*)d_out;

    fused_kernel<<<512, 128>>>(x, SU, SV, grid, Wscale, bias, Qidxs, out);
}

// round 17
// speedup vs baseline: 1.4252x; 1.4252x over previous
#include <cuda_runtime.h>
#include <cuda_fp16.h>
#include <cstdint>

#define TOKENS 64
#define IN_F   8192
#define OUT_F  8192
#define NGROUPS (IN_F / 8)     // 1024
#define KT_TILES (IN_F / 16)   // 512 k16 tiles
#define KSPLIT 4
#define NBLK   128             // outputs per block (4 warps x N32)
#define HALF_F 4096

// A fragments: [kt][mt][lane] -> uint4 (4 regs of m16k16 fp16 frag)
__device__ uint4 g_xa[KT_TILES * 4 * 32];            // 1 MB
// accumulated output [token][out] (REDG target, zeroed by fwht_in)
__device__ float g_acc[TOKENS * OUT_F];              // 2 MB
// readiness flags: chunk hb (kt<256 / kt>=256) -> #tokens published
__device__ int g_ready[2];

#define INV_SQRT_8192 0.011048543456039806f

__device__ __forceinline__ int SW(int i) {
    return (i & ~31) | ((i ^ (i >> 5)) & 31);
}
__device__ __forceinline__ int ld_vol(const int* p) {
    int v;
    asm volatile("ld.volatile.global.s32 %0, [%1];" : "=r"(v) : "l"(p) : "memory");
    return v;
}

#define FWHT_REG(a, N)                                            \
    _Pragma("unroll")                                             \
    for (int h = 1; h < (N); h <<= 1) {                           \
        _Pragma("unroll")                                         \
        for (int i = 0; i < (N); i++) {                           \
            if (!(i & h)) {                                       \
                float u = a[i], v = a[i ^ h];                     \
                a[i] = u + v; a[i ^ h] = u - v;                   \
            }                                                     \
        }                                                         \
    }

#define FWHT4096_BODY(s, tid, a, c)                               \
    FWHT_REG(a, 16)                                               \
    _Pragma("unroll")                                             \
    for (int j = 0; j < 16; j++)                                  \
        s[SW(tid + 256 * j)] = a[j];                              \
    __syncthreads();                                              \
    {                                                             \
        const int lo = tid & 15, hi = tid >> 4;                   \
        float bb[16];                                             \
        _Pragma("unroll")                                         \
        for (int j = 0; j < 16; j++)                              \
            bb[j] = s[SW(hi * 256 + j * 16 + lo)];                \
        FWHT_REG(bb, 16)                                          \
        __syncthreads();                                          \
        _Pragma("unroll")                                         \
        for (int j = 0; j < 16; j++)                              \
            s[SW(hi * 256 + j * 16 + lo)] = bb[j];                \
    }                                                             \
    __syncthreads();                                              \
    _Pragma("unroll")                                             \
    for (int i = 0; i < 16; i++)                                  \
        c[i] = s[SW(tid * 16 + i)];                               \
    FWHT_REG(c, 16)

// ---------------------------------------------------------------------------
// Kernel A: zero g_acc slice + FWHT(x*SU)*scale -> fp16 A-fragments.
// 2 blocks per token. Publishes its kt-chunk via g_ready[hb].
// ---------------------------------------------------------------------------
__global__ __launch_bounds__(256) void fwht_in_kernel(
    const float* __restrict__ x,
    const float* __restrict__ SU,
    const float* __restrict__ Wscale)
{
    cudaTriggerProgrammaticLaunchCompletion();

    __shared__ float s[HALF_F];               // 16 KB
    const int t   = blockIdx.x >> 1;
    const int hb  = blockIdx.x & 1;
    const int tid = threadIdx.x;
    const float* xr = x + (size_t)t * IN_F;

    // zero this block's 16 KB slice of g_acc (4096 floats)
    {
        float4* z = (float4*)(g_acc + (size_t)blockIdx.x * 4096) + tid;
#pragma unroll
        for (int v = 0; v < 4; v++)
            z[v * 256] = make_float4(0.f, 0.f, 0.f, 0.f);
    }

    float a[16];
#pragma unroll
    for (int j = 0; j < 16; j++) {
        const int i = tid + 256 * j;
        const float v0 = xr[i] * SU[i];
        const float v1 = xr[i + HALF_F] * SU[i + HALF_F];
        a[j] = hb ? (v0 - v1) : (v0 + v1);
    }

    float c[16];
    FWHT4096_BODY(s, tid, a, c)

    const float scale = INV_SQRT_8192 * Wscale[0];
    const int mt   = t >> 4;
    const int mrow = t & 15;
    const int kt   = hb * 256 + tid;          // this thread's k16 tile
    uint32_t* xa = (uint32_t*)g_xa;
#pragma unroll
    for (int p = 0; p < 8; p++) {
        const int r    = p >> 2;
        const int lane = ((mrow & 7) << 2) | (p & 3);
        const int reg  = (r << 1) | (mrow >> 3);
        __half2 h = __floats2half2_rn(c[2 * p] * scale, c[2 * p + 1] * scale);
        xa[(((kt * 4 + mt) * 32 + lane) << 2) + reg] = *(uint32_t*)&h;
    }

    __syncthreads();
    if (tid == 0) {
        __threadfence();                       // release g_xa chunk + g_acc zeroes
        atomicAdd(&g_ready[hb], 1);
    }
}

// ---------------------------------------------------------------------------
// Kernel B: fused codebook-decode + fp16 mma.sync GEMM.
// Warp tile M64 x N32 (4 n-tiles) -> 16 MMAs per kt per warp; Qidxs via
// int4 (2 kt per load). Cuts L1TEX wavefronts/MMA ~1.6x vs N16 tile.
// ---------------------------------------------------------------------------
__device__ __forceinline__ void mma16816(float c[4], const uint4& a,
                                         uint32_t b0, uint32_t b1)
{
    asm volatile(
        "mma.sync.aligned.m16n8k16.row.col.f32.f16.f16.f32 "
        "{%0,%1,%2,%3},{%4,%5,%6,%7},{%8,%9},{%0,%1,%2,%3};\n"
        : "+f"(c[0]), "+f"(c[1]), "+f"(c[2]), "+f"(c[3])
        : "r"(a.x), "r"(a.y), "r"(a.z), "r"(a.w), "r"(b0), "r"(b1));
}

__global__ __launch_bounds__(128) void gemm_kernel(
    const int*   __restrict__ Qidxs,
    const float* __restrict__ grid)
{
    __shared__ uint32_t cb[256 * 4];     // codebook as half2: [code][pair]
    const int tid = threadIdx.x;
    // prologue (independent of fwht_in)
    for (int i = tid; i < 1024; i += 128) {
        int c = i >> 2, j = i & 3;
        __half2 h = __floats2half2_rn(grid[c * 8 + 2 * j], grid[c * 8 + 2 * j + 1]);
        cb[i] = *(uint32_t*)&h;
    }

    const int lane = tid & 31;
    const int w    = tid >> 5;
    const int l4   = lane & 3;
    const int lq   = lane >> 2;
    const int oW   = blockIdx.x * NBLK + w * 32;   // warp's 32 outputs
    const int split = blockIdx.y;

    const int ktBase = split * (KT_TILES / KSPLIT);   // 128 tiles per split
    const int ktEnd  = ktBase + (KT_TILES / KSPLIT);

    const int* qp[4];
#pragma unroll
    for (int nt = 0; nt < 4; nt++)
        qp[nt] = Qidxs + (size_t)(oW + nt * 8 + lq) * NGROUPS;

    // Qidxs prefetch (independent of fwht_in): int4 = 4 groups = 2 kt
    int4 qv[4], qn[4];
#pragma unroll
    for (int nt = 0; nt < 4; nt++)
        qv[nt] = *(const int4*)(qp[nt] + ktBase * 2);

    float acc[4][4][4];                  // [ntile][mtile][reg]
#pragma unroll
    for (int nt = 0; nt < 4; nt++)
#pragma unroll
        for (int m = 0; m < 4; m++)
#pragma unroll
            for (int r = 0; r < 4; r++) acc[nt][m][r] = 0.0f;

    // wait for THIS split's kt-chunk
    if (tid == 0) {
        const int chunk = split >> 1;            // kt<256 -> 0, else 1
        while (ld_vol(&g_ready[chunk]) < TOKENS) __nanosleep(100);
    }
    __syncthreads();                             // cb visible + chunk ready

    uint4 aB[2][4];
#pragma unroll
    for (int m = 0; m < 4; m++) {
        aB[0][m] = g_xa[((ktBase    ) * 4 + m) * 32 + lane];
        aB[1][m] = g_xa[((ktBase + 1) * 4 + m) * 32 + lane];
    }

    for (int kt = ktBase; kt < ktEnd; kt += 2) {
        // prefetch q for the next 2-kt step
        const int ktp = (kt + 2 < ktEnd) ? kt + 2 : ktBase;
#pragma unroll
        for (int nt = 0; nt < 4; nt++)
            qn[nt] = *(const int4*)(qp[nt] + ktp * 2);

        // ---- sub-iter 0: kt (groups .x, .y) ----
        {
            uint32_t b0[4], b1[4];
#pragma unroll
            for (int nt = 0; nt < 4; nt++) {
                b0[nt] = cb[(qv[nt].x << 2) | l4];
                b1[nt] = cb[(qv[nt].y << 2) | l4];
            }
#pragma unroll
            for (int m = 0; m < 4; m++)
#pragma unroll
                for (int nt = 0; nt < 4; nt++)
                    mma16816(acc[nt][m], aB[0][m], b0[nt], b1[nt]);
            const int ktn = (kt + 2 < ktEnd) ? kt + 2 : ktEnd - 1;
#pragma unroll
            for (int m = 0; m < 4; m++)
                aB[0][m] = g_xa[(ktn * 4 + m) * 32 + lane];
        }
        // ---- sub-iter 1: kt+1 (groups .z, .w) ----
        {
            uint32_t b0[4], b1[4];
#pragma unroll
            for (int nt = 0; nt < 4; nt++) {
                b0[nt] = cb[(qv[nt].z << 2) | l4];
                b1[nt] = cb[(qv[nt].w << 2) | l4];
            }
#pragma unroll
            for (int m = 0; m < 4; m++)
#pragma unroll
                for (int nt = 0; nt < 4; nt++)
                    mma16816(acc[nt][m], aB[1][m], b0[nt], b1[nt]);
            const int ktn = (kt + 3 < ktEnd) ? kt + 3 : ktEnd - 1;
#pragma unroll
            for (int m = 0; m < 4; m++)
                aB[1][m] = g_xa[(ktn * 4 + m) * 32 + lane];
        }
#pragma unroll
        for (int nt = 0; nt < 4; nt++) qv[nt] = qn[nt];
    }

    // full wait (guards g_acc zeroing) -- trivially satisfied by now
    if (tid == 0) {
        while (ld_vol(&g_ready[0]) < TOKENS ||
               ld_vol(&g_ready[1]) < TOKENS) __nanosleep(100);
    }
    __syncthreads();

    // epilogue: REDG accumulate
#pragma unroll
    for (int nt = 0; nt < 4; nt++) {
        const int o = oW + nt * 8 + 2 * l4;
#pragma unroll
        for (int m = 0; m < 4; m++) {
            const int t0 = m * 16 + lq;
            atomicAdd(&g_acc[(size_t)t0 * OUT_F + o],           acc[nt][m][0]);
            atomicAdd(&g_acc[(size_t)t0 * OUT_F + o + 1],       acc[nt][m][1]);
            atomicAdd(&g_acc[(size_t)(t0 + 8) * OUT_F + o],     acc[nt][m][2]);
            atomicAdd(&g_acc[(size_t)(t0 + 8) * OUT_F + o + 1], acc[nt][m][3]);
        }
    }

    cudaTriggerProgrammaticLaunchCompletion();
}

// ---------------------------------------------------------------------------
// Kernel C: read accumulated g_acc (folded stride-4096 butterfly),
// FWHT_4096, * SV/sqrt + bias. 2 blocks per token. PDL consumer.
// Resets g_ready for the next graph replay.
// ---------------------------------------------------------------------------
__global__ __launch_bounds__(256) void fwht_out_kernel(
    const float* __restrict__ SV,
    const float* __restrict__ bias,
    float* __restrict__ out)
{
    __shared__ float s[HALF_F];
    const int t   = blockIdx.x >> 1;
    const int hb  = blockIdx.x & 1;
    const int tid = threadIdx.x;

    cudaGridDependencySynchronize();

    if (blockIdx.x == 0 && tid == 0) {
        g_ready[0] = 0;
        g_ready[1] = 0;
    }

    const float* row = g_acc + (size_t)t * OUT_F;
    float a[16];
#pragma unroll
    for (int j = 0; j < 16; j++) {
        const int i = tid + 256 * j;
        const float v0 = row[i];
        const float v1 = row[i + HALF_F];
        a[j] = hb ? (v0 - v1) : (v0 + v1);
    }

    float c[16];
    FWHT4096_BODY(s, tid, a, c)

    float* orow = out + (size_t)t * OUT_F + hb * HALF_F;
#pragma unroll
    for (int i = 0; i < 16; i++) {
        const int idx = tid * 16 + i;
        const int gidx = hb * HALF_F + idx;
        orow[idx] = c[i] * INV_SQRT_8192 * SV[gidx] + bias[gidx];
    }
}

// ---------------------------------------------------------------------------
// Inputs (metadata order): x, SU, SV, grid, Wscale, bias, Qidxs
// ---------------------------------------------------------------------------
extern "C" void kernel_launch(void* const* d_in, const int* in_sizes, int n_in,
                              void* d_out, int out_size)
{
    const float* x      = (const float*)d_in[0];
    const float* SU     = (const float*)d_in[1];
    const float* SV     = (const float*)d_in[2];
    const float* grid   = (const float*)d_in[3];
    const float* Wscale = (const float*)d_in[4];
    const float* bias   = (const float*)d_in[5];
    const int*   Qidxs  = (const int*)  d_in[6];
    float*       out    = (float*)d_out;

    fwht_in_kernel<<<2 * TOKENS, 256>>>(x, SU, Wscale);

    {
        cudaLaunchConfig_t cfg = {};
        cfg.gridDim  = dim3(OUT_F / NBLK, KSPLIT, 1);
        cfg.blockDim = dim3(128, 1, 1);
        cudaLaunchAttribute attr[1];
        attr[0].id = cudaLaunchAttributeProgrammaticStreamSerialization;
        attr[0].val.programmaticStreamSerializationAllowed = 1;
        cfg.attrs = attr;
        cfg.numAttrs = 1;
        cudaLaunchKernelEx(&cfg, gemm_kernel, Qidxs, grid);
    }

    {
        cudaLaunchConfig_t cfg = {};
        cfg.gridDim  = dim3(2 * TOKENS, 1, 1);
        cfg.blockDim = dim3(256, 1, 1);
        cudaLaunchAttribute attr[1];
        attr[0].id = cudaLaunchAttributeProgrammaticStreamSerialization;
        attr[0].val.programmaticStreamSerializationAllowed = 1;
        cfg.attrs = attr;
        cfg.numAttrs = 1;
        cudaLaunchKernelEx(&cfg, fwht_out_kernel, SV, bias, out);
    }
}